// round 5
// baseline (speedup 1.0000x reference)
#include <cuda_runtime.h>
#include <cuda_bf16.h>
#include <cstdint>

#define SM_STRIDE 136            // bf16 elems per smem row (conflict-free ldmatrix)

// ---------------- smem layout (bytes) ----------------
#define WS_HI_OFF 0                          // W hi: 128*136*2 = 34816
#define WS_LO_OFF 34816                      // W lo
#define XS_OFF    69632                      // 8 pair buffers
#define XS_PAIR   17408                      // per pair: hi 8704 + lo 8704
#define XN2_OFF   (XS_OFF + 8*XS_PAIR)       // float[8][32]  (208896)
#define HV_OFF    (XN2_OFF + 1024)           // float[128]
#define RED1_OFF  (HV_OFF + 512)             // float2[16][32] = 4096
#define RED2_OFF  (RED1_OFF + 4096)          // float[16][32]  = 2048
#define SC_OFF    (RED2_OFF + 2048)
#define SMEM_BYTES (SC_OFF + 16)             // ~211.5 KB -> 1 CTA/SM

#define MINN  1e-15f
#define MAXN  0.996f
#define ATLIM (1.0f - 1e-7f)

__device__ __forceinline__ unsigned int bfu(__nv_bfloat16 h) {
    return (unsigned int)*reinterpret_cast<unsigned short*>(&h);
}

#define LDSM4(R, addr)                                                        \
    asm volatile("ldmatrix.sync.aligned.m8n8.x4.shared.b16 {%0,%1,%2,%3}, [%4];" \
                 : "=r"((R)[0]), "=r"((R)[1]), "=r"((R)[2]), "=r"((R)[3])     \
                 : "r"(addr) : "memory")

#define PAIR_BAR() asm volatile("bar.sync %0, 64;" :: "r"(barid) : "memory")

__device__ __forceinline__ void mma16816(float* d, const uint32_t* a, const uint32_t* b) {
    asm volatile(
        "mma.sync.aligned.m16n8k16.row.col.f32.bf16.bf16.f32 "
        "{%0,%1,%2,%3}, {%4,%5,%6,%7}, {%8,%9}, {%0,%1,%2,%3};"
        : "+f"(d[0]), "+f"(d[1]), "+f"(d[2]), "+f"(d[3])
        : "r"(a[0]), "r"(a[1]), "r"(a[2]), "r"(a[3]), "r"(b[0]), "r"(b[1]));
}

__device__ __forceinline__ float artanh_c(float x) {
    float xc = fminf(x, ATLIM);
    return 0.5f * (log1pf(xc) - log1pf(-xc));
}

__device__ __forceinline__ void row_chain(float S2, float D, float xn2v, float y2,
                                          float& pa, float& pb, float& Lr) {
    float xn  = fmaxf(sqrtf(xn2v), MINN);
    float mxn = fmaxf(sqrtf(S2), MINN);
    float atx = artanh_c(xn);
    float r1  = tanhf(mxn / xn * atx);
    float scale1 = r1 / mxn;
    float resn = r1;
    float pn = fmaxf(resn, MINN);
    if (pn > MAXN) { scale1 *= MAXN / pn; resn = MAXN; }
    float x2 = resn * resn;
    float xy = scale1 * D;
    float num1 = 1.f + 2.f*xy + y2;
    float den  = fmaxf(1.f + 2.f*xy + x2*y2, MINN);
    float aC = num1 / den;
    float bC = (1.f - x2) / den;
    float o2n2 = aC*aC*x2 + 2.f*aC*bC*xy + bC*bC*y2;
    float o2n  = sqrtf(fmaxf(o2n2, 0.f));
    float g = 1.f;
    float pn2 = fmaxf(o2n, MINN);
    if (pn2 > MAXN) { g = MAXN / pn2; pn2 = MAXN; }
    Lr = artanh_c(pn2) / pn2;
    pa = g * aC * scale1;
    pb = g * bC;
}

__device__ __forceinline__ float final_scale(float ps, float Lr) {
    float P  = sqrtf(fmaxf(ps, 0.f));
    float un = fmaxf(Lr * P, MINN);
    float th = tanhf(un);
    float f  = th / un * Lr;
    if (th > MAXN) f *= MAXN / th;
    return f;
}

// fp32x4 -> bf16 hi/lo into padded-stride smem (row*SM_STRIDE + col)
__device__ __forceinline__ void store_split(__nv_bfloat16* hi, __nv_bfloat16* lo,
                                            int row, int col, float4 v) {
    __nv_bfloat16 h0 = __float2bfloat16(v.x), h1 = __float2bfloat16(v.y);
    __nv_bfloat16 h2 = __float2bfloat16(v.z), h3 = __float2bfloat16(v.w);
    __nv_bfloat16 l0 = __float2bfloat16(v.x - __bfloat162float(h0));
    __nv_bfloat16 l1 = __float2bfloat16(v.y - __bfloat162float(h1));
    __nv_bfloat16 l2 = __float2bfloat16(v.z - __bfloat162float(h2));
    __nv_bfloat16 l3 = __float2bfloat16(v.w - __bfloat162float(h3));
    uint2 ph, pl;
    ph.x = bfu(h0) | (bfu(h1) << 16); ph.y = bfu(h2) | (bfu(h3) << 16);
    pl.x = bfu(l0) | (bfu(l1) << 16); pl.y = bfu(l2) | (bfu(l3) << 16);
    *(uint2*)(hi + row * SM_STRIDE + col) = ph;
    *(uint2*)(lo + row * SM_STRIDE + col) = pl;
}

__global__ void __launch_bounds__(512, 1)
blinear_fused(const float* __restrict__ X, const float* __restrict__ W,
              const float* __restrict__ B, float* __restrict__ OUT, int nTiles)
{
    extern __shared__ char smem[];
    __nv_bfloat16* ws_hi = (__nv_bfloat16*)(smem + WS_HI_OFF);
    __nv_bfloat16* ws_lo = (__nv_bfloat16*)(smem + WS_LO_OFF);
    float*  xn2_s = (float*)(smem + XN2_OFF);
    float*  hvec  = (float*)(smem + HV_OFF);
    float2* red1  = (float2*)(smem + RED1_OFF);
    float*  red2  = (float*)(smem + RED2_OFF);
    float*  SC    = (float*)(smem + SC_OFF);

    const int tid  = threadIdx.x;
    const int lane = tid & 31;
    const int w    = tid >> 5;   // 0..15
    const int pr   = w >> 1;     // pair 0..7
    const int wh   = w & 1;      // col half (64 cols)
    const int tq   = lane & 3;
    const int q    = lane >> 2;
    const int barid = 1 + pr;
    const int slot  = pr * 2 + wh;

    __nv_bfloat16* xs_hi = (__nv_bfloat16*)(smem + XS_OFF + pr * XS_PAIR);
    __nv_bfloat16* xs_lo = (__nv_bfloat16*)(smem + XS_OFF + pr * XS_PAIR + 8704);
    float* xn2p = xn2_s + pr * 32;

    // ---- once per CTA (= once per SM): W -> bf16 hi/lo ----
    #pragma unroll
    for (int j = 0; j < 8; ++j) {
        int row = j * 16 + w;
        float4 wv = *(const float4*)(W + (size_t)row * 128 + lane * 4);
        store_split(ws_hi, ws_lo, row, lane * 4, wv);
    }

    // ---- once: hyp bias h = proj(expmap0(b)) (warp 0) ----
    if (w == 0) {
        float4 bv = *(const float4*)(B + lane * 4);
        float sq = bv.x*bv.x + bv.y*bv.y + bv.z*bv.z + bv.w*bv.w;
        #pragma unroll
        for (int o = 16; o; o >>= 1) sq += __shfl_xor_sync(0xffffffffu, sq, o);
        float bn2 = sq;
        float bn  = fmaxf(sqrtf(bn2), MINN);
        float th  = tanhf(bn);
        float hs  = th / bn;
        float hn  = hs * sqrtf(bn2);
        float pn  = fmaxf(hn, MINN);
        if (pn > MAXN) hs *= MAXN / pn;
        if (lane == 0) SC[0] = hs * hs * bn2;
        *(float4*)(hvec + lane * 4) =
            make_float4(hs*bv.x, hs*bv.y, hs*bv.z, hs*bv.w);
    }
    __syncthreads();

    const float y2 = SC[0];

    // fragment smem addresses
    uint32_t s_xhi = (uint32_t)__cvta_generic_to_shared(xs_hi);
    uint32_t s_xlo = (uint32_t)__cvta_generic_to_shared(xs_lo);
    uint32_t s_whi = (uint32_t)__cvta_generic_to_shared(ws_hi);
    uint32_t s_wlo = (uint32_t)__cvta_generic_to_shared(ws_lo);

    // A: two m16 frags covering 32 rows
    const uint32_t aoff0 = (uint32_t)((((lane & 15)) * SM_STRIDE + (lane >> 4) * 8) * 2);
    const uint32_t aoff1 = aoff0 + 16 * SM_STRIDE * 2;
    // B: 4 n16 groups covering this warp's 64 cols
    const int bg  = lane >> 3;
    const int b_n = ((bg >> 1) << 3) + (lane & 7);
    const int b_k = (bg & 1) * 8;
    uint32_t boff[4];
    #pragma unroll
    for (int g = 0; g < 4; ++g)
        boff[g] = (uint32_t)(((64*wh + 16*g + b_n) * SM_STRIDE + b_k) * 2);

    const int stride = gridDim.x * 8;

    // ================= persistent tile loop (32-row tiles per pair) ========
    for (int tile = blockIdx.x * 8 + pr; tile < nTiles; tile += stride) {
        const size_t tileRow = (size_t)tile * 32;

        // ---- load this warp's 16 rows, norms, bf16 split ----
        #pragma unroll
        for (int j = 0; j < 16; ++j) {
            int rloc = 16*wh + j;
            float4 v = *(const float4*)(X + (tileRow + rloc) * 128 + lane * 4);
            float sq = v.x*v.x + v.y*v.y + v.z*v.z + v.w*v.w;
            #pragma unroll
            for (int o = 16; o; o >>= 1) sq += __shfl_xor_sync(0xffffffffu, sq, o);
            if (lane == 0) xn2p[rloc] = sq;
            store_split(xs_hi, xs_lo, rloc, lane * 4, v);
        }

        // L2 prefetch of next tile's 16 rows for this warp
        {
            int nt2 = tile + stride;
            if (nt2 < nTiles) {
                const float* pf = X + ((size_t)nt2 * 32 + 16*wh) * 128 + (size_t)lane * 64;
                asm volatile("prefetch.global.L2 [%0];" :: "l"(pf));
                asm volatile("prefetch.global.L2 [%0];" :: "l"(pf + 32));
            }
        }

        PAIR_BAR();   // A: xs + xn2 visible within pair

        // ---- MMA: 32 rows x 64 cols, 3-term bf16 split ----
        float acc[2][8][4];
        #pragma unroll
        for (int mt = 0; mt < 2; ++mt)
            #pragma unroll
            for (int ng = 0; ng < 8; ++ng)
                #pragma unroll
                for (int r = 0; r < 4; ++r) acc[mt][ng][r] = 0.f;

        #pragma unroll
        for (int k = 0; k < 8; ++k) {
            const uint32_t kb = k * 32;
            uint32_t ah[2][4], al[2][4];
            LDSM4(ah[0], s_xhi + aoff0 + kb);
            LDSM4(ah[1], s_xhi + aoff1 + kb);
            LDSM4(al[0], s_xlo + aoff0 + kb);
            LDSM4(al[1], s_xlo + aoff1 + kb);
            #pragma unroll
            for (int half = 0; half < 2; ++half) {
                uint32_t bh[2][4], bl[2][4];
                LDSM4(bh[0], s_whi + boff[2*half]   + kb);
                LDSM4(bh[1], s_whi + boff[2*half+1] + kb);
                LDSM4(bl[0], s_wlo + boff[2*half]   + kb);
                LDSM4(bl[1], s_wlo + boff[2*half+1] + kb);
                #pragma unroll
                for (int mt = 0; mt < 2; ++mt)
                    #pragma unroll
                    for (int nn = 0; nn < 4; ++nn) {
                        const int ng = half*4 + nn;
                        const int g = nn >> 1, o = (nn & 1) * 2;
                        mma16816(acc[mt][ng], ah[mt], &bh[g][o]);
                        mma16816(acc[mt][ng], ah[mt], &bl[g][o]);
                        mma16816(acc[mt][ng], al[mt], &bh[g][o]);
                    }
            }
        }

        // ---- epilogue: h slice for this warp's 64 cols ----
        float hv[8][2];
        #pragma unroll
        for (int ng = 0; ng < 8; ++ng) {
            float2 hc = *(const float2*)(hvec + 64*wh + 8*ng + 2*tq);
            hv[ng][0] = hc.x; hv[ng][1] = hc.y;
        }

        // phase 1: per-row partial sum(mx^2), sum(mx*h) (4 rows/thread)
        float S2r[2][2], Dr[2][2];
        #pragma unroll
        for (int mt = 0; mt < 2; ++mt)
            #pragma unroll
            for (int rh = 0; rh < 2; ++rh) {
                float sq = 0.f, dh = 0.f;
                #pragma unroll
                for (int ng = 0; ng < 8; ++ng) {
                    float v0 = acc[mt][ng][2*rh], v1 = acc[mt][ng][2*rh + 1];
                    sq = fmaf(v0, v0, fmaf(v1, v1, sq));
                    dh = fmaf(v0, hv[ng][0], fmaf(v1, hv[ng][1], dh));
                }
                sq += __shfl_xor_sync(0xffffffffu, sq, 1);
                sq += __shfl_xor_sync(0xffffffffu, sq, 2);
                dh += __shfl_xor_sync(0xffffffffu, dh, 1);
                dh += __shfl_xor_sync(0xffffffffu, dh, 2);
                S2r[mt][rh] = sq; Dr[mt][rh] = dh;
                if (tq == 0) red1[slot * 32 + 16*mt + 8*rh + q] = make_float2(sq, dh);
            }
        PAIR_BAR();   // B

        // chain (per-quad redundant; MUFU is off the L1 critical path)
        float pa[2][2], pb[2][2], Lr[2][2];
        #pragma unroll
        for (int mt = 0; mt < 2; ++mt)
            #pragma unroll
            for (int rh = 0; rh < 2; ++rh) {
                int rloc = 16*mt + 8*rh + q;
                float2 ot = red1[(pr*2 + (wh^1)) * 32 + rloc];
                row_chain(S2r[mt][rh] + ot.x, Dr[mt][rh] + ot.y,
                          xn2p[rloc], y2, pa[mt][rh], pb[mt][rh], Lr[mt][rh]);
            }

        // phase 2: val = pa*mx + pb*h ; sum(relu^2)
        float psr[2][2];
        #pragma unroll
        for (int mt = 0; mt < 2; ++mt)
            #pragma unroll
            for (int rh = 0; rh < 2; ++rh) {
                float ps = 0.f;
                float pav = pa[mt][rh], pbv = pb[mt][rh];
                #pragma unroll
                for (int ng = 0; ng < 8; ++ng) {
                    float v0 = fmaf(pav, acc[mt][ng][2*rh],     pbv * hv[ng][0]);
                    float v1 = fmaf(pav, acc[mt][ng][2*rh + 1], pbv * hv[ng][1]);
                    acc[mt][ng][2*rh]     = v0;
                    acc[mt][ng][2*rh + 1] = v1;
                    float p0 = fmaxf(v0, 0.f), p1 = fmaxf(v1, 0.f);
                    ps = fmaf(p0, p0, fmaf(p1, p1, ps));
                }
                ps += __shfl_xor_sync(0xffffffffu, ps, 1);
                ps += __shfl_xor_sync(0xffffffffu, ps, 2);
                psr[mt][rh] = ps;
                if (tq == 0) red2[slot * 32 + 16*mt + 8*rh + q] = ps;
            }
        PAIR_BAR();   // C

        // final scale + store
        #pragma unroll
        for (int mt = 0; mt < 2; ++mt)
            #pragma unroll
            for (int rh = 0; rh < 2; ++rh) {
                int rloc = 16*mt + 8*rh + q;
                float fs = final_scale(psr[mt][rh] + red2[(pr*2 + (wh^1)) * 32 + rloc],
                                       Lr[mt][rh]);
                float* outp = OUT + (tileRow + rloc) * 128 + 64*wh + 2*tq;
                #pragma unroll
                for (int ng = 0; ng < 8; ++ng) {
                    float2 o;
                    o.x = fs * fmaxf(acc[mt][ng][2*rh],     0.f);
                    o.y = fs * fmaxf(acc[mt][ng][2*rh + 1], 0.f);
                    *(float2*)(outp + 8*ng) = o;
                }
            }
        // cross-iteration smem reuse ordered by the three pair barriers
    }
}

extern "C" void kernel_launch(void* const* d_in, const int* in_sizes, int n_in,
                              void* d_out, int out_size) {
    const float* x = (const float*)d_in[0];
    const float* W = (const float*)d_in[1];
    const float* b = (const float*)d_in[2];
    float* out = (float*)d_out;

    int nRows  = in_sizes[0] / 128;      // 524288
    int nTiles = nRows / 32;             // 16384

    int sms = 148;
    cudaDeviceGetAttribute(&sms, cudaDevAttrMultiProcessorCount, 0);
    int grid = sms;
    if (grid * 8 > nTiles) grid = (nTiles + 7) / 8;

    cudaFuncSetAttribute(blinear_fused,
                         cudaFuncAttributeMaxDynamicSharedMemorySize, SMEM_BYTES);
    blinear_fused<<<grid, 512, SMEM_BYTES>>>(x, W, b, out, nTiles);
}

// round 6
// speedup vs baseline: 1.0875x; 1.0875x over previous
#include <cuda_runtime.h>
#include <cuda_bf16.h>
#include <cstdint>

#define SM_STRIDE 136            // bf16 elems per smem row (conflict-free ldmatrix)

// smem byte offsets
#define WHI_OFF   0
#define WLO_OFF   (WHI_OFF + 128 * SM_STRIDE * 2)
#define XHI_OFF   (WLO_OFF + 128 * SM_STRIDE * 2)
#define XLO_OFF   (XHI_OFF + 64 * SM_STRIDE * 2)
#define XN2_OFF   (XLO_OFF + 64 * SM_STRIDE * 2)   // float[64]
#define HV_OFF    (XN2_OFF + 256)                  // float[128]
#define RED1_OFF  (HV_OFF  + 512)                  // float4[4][2][8] = 1024 B
#define RED2_OFF  (RED1_OFF + 1024)                // float2[4][2][8] = 512 B
#define SC_OFF    (RED2_OFF + 512)                 // float[4]
#define SMEM_BYTES (SC_OFF + 16)                   // ~104.3 KB -> 2 CTAs/SM

#define MINN  1e-15f
#define MAXN  0.996f
#define ATLIM (1.0f - 1e-7f)

#define LDSM4(R, addr)                                                        \
    asm volatile("ldmatrix.sync.aligned.m8n8.x4.shared.b16 {%0,%1,%2,%3}, [%4];" \
                 : "=r"((R)[0]), "=r"((R)[1]), "=r"((R)[2]), "=r"((R)[3])     \
                 : "r"(addr) : "memory")

#define PAIR_BAR() asm volatile("bar.sync %0, 64;" :: "r"(barid) : "memory")

__device__ __forceinline__ void mma16816(float* d, const uint32_t* a, const uint32_t* b) {
    asm volatile(
        "mma.sync.aligned.m16n8k16.row.col.f32.bf16.bf16.f32 "
        "{%0,%1,%2,%3}, {%4,%5,%6,%7}, {%8,%9}, {%0,%1,%2,%3};"
        : "+f"(d[0]), "+f"(d[1]), "+f"(d[2]), "+f"(d[3])
        : "r"(a[0]), "r"(a[1]), "r"(a[2]), "r"(a[3]), "r"(b[0]), "r"(b[1]));
}

__device__ __forceinline__ float artanh_c(float x) {
    float xc = fminf(x, ATLIM);
    return 0.5f * (log1pf(xc) - log1pf(-xc));
}

__device__ __forceinline__ void row_chain(float S2, float D, float xn2v, float y2,
                                          float& pa, float& pb, float& Lr) {
    float xn  = fmaxf(sqrtf(xn2v), MINN);
    float mxn = fmaxf(sqrtf(S2), MINN);
    float atx = artanh_c(xn);
    float r1  = tanhf(mxn / xn * atx);
    float scale1 = r1 / mxn;
    float resn = r1;
    float pn = fmaxf(resn, MINN);
    if (pn > MAXN) { scale1 *= MAXN / pn; resn = MAXN; }
    float x2 = resn * resn;
    float xy = scale1 * D;
    float num1 = 1.f + 2.f*xy + y2;
    float den  = fmaxf(1.f + 2.f*xy + x2*y2, MINN);
    float aC = num1 / den;
    float bC = (1.f - x2) / den;
    float o2n2 = aC*aC*x2 + 2.f*aC*bC*xy + bC*bC*y2;
    float o2n  = sqrtf(fmaxf(o2n2, 0.f));
    float g = 1.f;
    float pn2 = fmaxf(o2n, MINN);
    if (pn2 > MAXN) { g = MAXN / pn2; pn2 = MAXN; }
    Lr = artanh_c(pn2) / pn2;
    pa = g * aC * scale1;
    pb = g * bC;
}

__device__ __forceinline__ float final_scale(float ps, float Lr) {
    float P  = sqrtf(fmaxf(ps, 0.f));
    float un = fmaxf(Lr * P, MINN);
    float th = tanhf(un);
    float f  = th / un * Lr;
    if (th > MAXN) f *= MAXN / th;
    return f;
}

// fast bf16 hi/lo split: hi = truncation (PRMT pack), lo = exact remainder, rn
__device__ __forceinline__ void split_store(__nv_bfloat16* hi, __nv_bfloat16* lo,
                                            int row, int col, float4 v) {
    uint32_t ux = __float_as_uint(v.x), uy = __float_as_uint(v.y);
    uint32_t uz = __float_as_uint(v.z), uw = __float_as_uint(v.w);
    uint2 ph;
    ph.x = __byte_perm(ux, uy, 0x7632);   // {bf16_trunc(x), bf16_trunc(y)}
    ph.y = __byte_perm(uz, uw, 0x7632);
    float rx = v.x - __uint_as_float(ux & 0xffff0000u);   // exact remainders
    float ry = v.y - __uint_as_float(uy & 0xffff0000u);
    float rz = v.z - __uint_as_float(uz & 0xffff0000u);
    float rw = v.w - __uint_as_float(uw & 0xffff0000u);
    __nv_bfloat162 l01 = __floats2bfloat162_rn(rx, ry);
    __nv_bfloat162 l23 = __floats2bfloat162_rn(rz, rw);
    uint2 pl;
    pl.x = *reinterpret_cast<uint32_t*>(&l01);
    pl.y = *reinterpret_cast<uint32_t*>(&l23);
    *(uint2*)(hi + row * SM_STRIDE + col) = ph;
    *(uint2*)(lo + row * SM_STRIDE + col) = pl;
}

__global__ void __launch_bounds__(256, 2)
blinear_fused(const float* __restrict__ X, const float* __restrict__ W,
              const float* __restrict__ B, float* __restrict__ OUT, int nTiles)
{
    extern __shared__ char smem[];
    __nv_bfloat16* ws_hi = (__nv_bfloat16*)(smem + WHI_OFF);
    __nv_bfloat16* ws_lo = (__nv_bfloat16*)(smem + WLO_OFF);
    __nv_bfloat16* xs_hi = (__nv_bfloat16*)(smem + XHI_OFF);
    __nv_bfloat16* xs_lo = (__nv_bfloat16*)(smem + XLO_OFF);
    float* xn2_s = (float*)(smem + XN2_OFF);
    float* hvec  = (float*)(smem + HV_OFF);
    float* red1  = (float*)(smem + RED1_OFF);
    float* red2  = (float*)(smem + RED2_OFF);
    float* SC    = (float*)(smem + SC_OFF);

    const int tid  = threadIdx.x;
    const int lane = tid & 31;
    const int w    = tid >> 5;   // 0..7
    const int pr   = w >> 1;     // pair 0..3 : rows 16*pr .. 16*pr+15
    const int wh   = w & 1;      // col half  : cols 64*wh .. 64*wh+63
    const int tq   = lane & 3;
    const int q    = lane >> 2;
    const int barid = 1 + pr;
    const int rbase = 16*pr + 8*wh;   // this warp's 8 x-rows within the tile

    // ---- once per CTA: convert W (128x128) to bf16 hi/lo in smem ----
    #pragma unroll
    for (int j = 0; j < 16; ++j) {
        int row = j * 8 + w;
        float4 wv = *(const float4*)(W + (size_t)row * 128 + lane * 4);
        split_store(ws_hi, ws_lo, row, lane * 4, wv);
    }

    // ---- once per CTA: hyp_bias h = proj(expmap0(b)) (warp 0) ----
    if (w == 0) {
        float4 bv = *(const float4*)(B + lane * 4);
        float sq = bv.x*bv.x + bv.y*bv.y + bv.z*bv.z + bv.w*bv.w;
        #pragma unroll
        for (int o = 16; o; o >>= 1) sq += __shfl_xor_sync(0xffffffffu, sq, o);
        float bn2 = sq;
        float bn  = fmaxf(sqrtf(bn2), MINN);
        float th  = tanhf(bn);
        float hs  = th / bn;
        float hn  = hs * sqrtf(bn2);
        float pn  = fmaxf(hn, MINN);
        if (pn > MAXN) hs *= MAXN / pn;
        if (lane == 0) SC[0] = hs * hs * bn2;
        *(float4*)(hvec + lane * 4) =
            make_float4(hs*bv.x, hs*bv.y, hs*bv.z, hs*bv.w);
    }
    __syncthreads();

    const float y2 = SC[0];

    // preload h slice for this warp's 64 columns (constant across tiles)
    float hv[8][2];
    #pragma unroll
    for (int nt = 0; nt < 8; ++nt) {
        int c = 64*wh + 8*nt + 2*tq;
        hv[nt][0] = hvec[c]; hv[nt][1] = hvec[c + 1];
    }

    uint32_t s_xhi = (uint32_t)__cvta_generic_to_shared(xs_hi);
    uint32_t s_xlo = (uint32_t)__cvta_generic_to_shared(xs_lo);
    uint32_t s_whi = (uint32_t)__cvta_generic_to_shared(ws_hi);
    uint32_t s_wlo = (uint32_t)__cvta_generic_to_shared(ws_lo);

    // A fragment address: pair rows 16*pr..16*pr+15
    const uint32_t aoff = (uint32_t)(((16*pr + (lane & 15)) * SM_STRIDE + (lane >> 4) * 8) * 2);
    // B fragment addresses: 4 n16-groups covering this warp's 64 cols
    const int bg  = lane >> 3;
    const int b_n = ((bg >> 1) << 3) + (lane & 7);
    const int b_k = (bg & 1) * 8;
    uint32_t boff[4];
    #pragma unroll
    for (int g = 0; g < 4; ++g)
        boff[g] = (uint32_t)(((64*wh + 16*g + b_n) * SM_STRIDE + b_k) * 2);

    // exchange buffer slots
    float4* r1_me = (float4*)(red1 + ((pr*2 + wh    )*8 + q) * 4);
    float4* r1_ot = (float4*)(red1 + ((pr*2 + (wh^1))*8 + q) * 4);
    float2* r2_me = (float2*)(red2 + ((pr*2 + wh    )*8 + q) * 2);
    float2* r2_ot = (float2*)(red2 + ((pr*2 + (wh^1))*8 + q) * 2);

    const int rl0 = 16*pr + q;       // local tile row for acc elems 0,1
    const int rl1 = rl0 + 8;         // local tile row for acc elems 2,3

    // ---- register pipeline buffer: this warp's 8 rows of the current tile ----
    float4 xr[8];
    if (blockIdx.x < nTiles) {
        const size_t rb = (size_t)blockIdx.x * 64 + rbase;
        #pragma unroll
        for (int j = 0; j < 8; ++j)
            xr[j] = *(const float4*)(X + (rb + j) * 128 + lane * 4);
    }

    // ================= persistent tile loop =================
    for (int tile = blockIdx.x; tile < nTiles; tile += gridDim.x) {
        const size_t tileRow = (size_t)tile * 64;

        // ---- convert xr (already loaded) : norms + bf16 split to smem ----
        #pragma unroll
        for (int j = 0; j < 8; ++j) {
            float4 v = xr[j];
            float sq = v.x*v.x + v.y*v.y + v.z*v.z + v.w*v.w;
            #pragma unroll
            for (int o = 16; o; o >>= 1) sq += __shfl_xor_sync(0xffffffffu, sq, o);
            if (lane == 0) xn2_s[rbase + j] = sq;
            split_store(xs_hi, xs_lo, rbase + j, lane * 4, v);
        }

        PAIR_BAR();   // A: xs + xn2 visible within pair

        // ---- MMA: bf16x2 split (hi*hi + hi*lo + lo*hi) ----
        float acc[8][4];
        #pragma unroll
        for (int nt = 0; nt < 8; ++nt)
            #pragma unroll
            for (int r = 0; r < 4; ++r) acc[nt][r] = 0.f;

        #pragma unroll
        for (int k = 0; k < 8; ++k) {
            const uint32_t kb = k * 32;
            uint32_t ah[4], al[4];
            LDSM4(ah, s_xhi + aoff + kb);
            LDSM4(al, s_xlo + aoff + kb);
            uint32_t bh[4][4], bl[4][4];
            #pragma unroll
            for (int g = 0; g < 4; ++g) {
                LDSM4(bh[g], s_whi + boff[g] + kb);
                LDSM4(bl[g], s_wlo + boff[g] + kb);
            }
            #pragma unroll
            for (int nt = 0; nt < 8; ++nt) {
                const int g = nt >> 1, o = (nt & 1) * 2;
                mma16816(acc[nt], ah, &bh[g][o]);
                mma16816(acc[nt], ah, &bl[g][o]);
                mma16816(acc[nt], al, &bh[g][o]);
            }
        }

        // ---- issue next tile's LDGs now: DRAM latency hides behind epilogue ----
        {
            int tn = tile + gridDim.x;
            if (tn < nTiles) {
                const size_t rb = (size_t)tn * 64 + rbase;
                #pragma unroll
                for (int j = 0; j < 8; ++j)
                    xr[j] = *(const float4*)(X + (rb + j) * 128 + lane * 4);
            }
        }

        // ---- phase 1: per-row sum(mx^2), sum(mx*h) over this warp's 64 cols ----
        float sq0 = 0.f, dh0 = 0.f, sq1 = 0.f, dh1 = 0.f;
        #pragma unroll
        for (int nt = 0; nt < 8; ++nt) {
            float v0 = acc[nt][0], v1 = acc[nt][1];
            float v2 = acc[nt][2], v3 = acc[nt][3];
            sq0 = fmaf(v0, v0, fmaf(v1, v1, sq0));
            dh0 = fmaf(v0, hv[nt][0], fmaf(v1, hv[nt][1], dh0));
            sq1 = fmaf(v2, v2, fmaf(v3, v3, sq1));
            dh1 = fmaf(v2, hv[nt][0], fmaf(v3, hv[nt][1], dh1));
        }
        #pragma unroll
        for (int o = 1; o <= 2; o <<= 1) {
            sq0 += __shfl_xor_sync(0xffffffffu, sq0, o);
            dh0 += __shfl_xor_sync(0xffffffffu, dh0, o);
            sq1 += __shfl_xor_sync(0xffffffffu, sq1, o);
            dh1 += __shfl_xor_sync(0xffffffffu, dh1, o);
        }
        if (tq == 0) *r1_me = make_float4(sq0, dh0, sq1, dh1);
        PAIR_BAR();   // B
        float4 ot = *r1_ot;
        float S2_0 = sq0 + ot.x, D0 = dh0 + ot.y;
        float S2_1 = sq1 + ot.z, D1 = dh1 + ot.w;

        // ---- per-row scalar chain (in registers, per-quad redundant) ----
        float pa0, pb0, Lr0, pa1, pb1, Lr1;
        row_chain(S2_0, D0, xn2_s[rl0], y2, pa0, pb0, Lr0);
        row_chain(S2_1, D1, xn2_s[rl1], y2, pa1, pb1, Lr1);

        // ---- phase 2: val = pa*mx + pb*h ; sum(relu(val)^2) ----
        float ps0 = 0.f, ps1 = 0.f;
        #pragma unroll
        for (int nt = 0; nt < 8; ++nt) {
            float v0 = fmaf(pa0, acc[nt][0], pb0 * hv[nt][0]);
            float v1 = fmaf(pa0, acc[nt][1], pb0 * hv[nt][1]);
            float v2 = fmaf(pa1, acc[nt][2], pb1 * hv[nt][0]);
            float v3 = fmaf(pa1, acc[nt][3], pb1 * hv[nt][1]);
            acc[nt][0] = v0; acc[nt][1] = v1; acc[nt][2] = v2; acc[nt][3] = v3;
            float p0 = fmaxf(v0, 0.f), p1 = fmaxf(v1, 0.f);
            float p2 = fmaxf(v2, 0.f), p3 = fmaxf(v3, 0.f);
            ps0 = fmaf(p0, p0, fmaf(p1, p1, ps0));
            ps1 = fmaf(p2, p2, fmaf(p3, p3, ps1));
        }
        #pragma unroll
        for (int o = 1; o <= 2; o <<= 1) {
            ps0 += __shfl_xor_sync(0xffffffffu, ps0, o);
            ps1 += __shfl_xor_sync(0xffffffffu, ps1, o);
        }
        if (tq == 0) *r2_me = make_float2(ps0, ps1);
        PAIR_BAR();   // C
        float2 ot2 = *r2_ot;
        float fs0 = final_scale(ps0 + ot2.x, Lr0);
        float fs1 = final_scale(ps1 + ot2.y, Lr1);

        // ---- store: out = fs * relu(val) ----
        float* outp = OUT + (tileRow + rl0) * 128 + 64*wh + 2*tq;
        #pragma unroll
        for (int nt = 0; nt < 8; ++nt) {
            float2 o0, o1;
            o0.x = fs0 * fmaxf(acc[nt][0], 0.f);
            o0.y = fs0 * fmaxf(acc[nt][1], 0.f);
            o1.x = fs1 * fmaxf(acc[nt][2], 0.f);
            o1.y = fs1 * fmaxf(acc[nt][3], 0.f);
            *(float2*)(outp + 8*nt)        = o0;
            *(float2*)(outp + 1024 + 8*nt) = o1;   // row rl1 = rl0 + 8
        }
        // cross-iteration smem reuse is ordered by the three pair barriers
    }
}

extern "C" void kernel_launch(void* const* d_in, const int* in_sizes, int n_in,
                              void* d_out, int out_size) {
    const float* x = (const float*)d_in[0];
    const float* W = (const float*)d_in[1];
    const float* b = (const float*)d_in[2];
    float* out = (float*)d_out;

    int nRows  = in_sizes[0] / 128;      // 524288
    int nTiles = nRows / 64;             // 8192

    int sms = 148;
    cudaDeviceGetAttribute(&sms, cudaDevAttrMultiProcessorCount, 0);
    int grid = 2 * sms;                  // 2 persistent CTAs per SM
    if (grid > nTiles) grid = nTiles;

    cudaFuncSetAttribute(blinear_fused,
                         cudaFuncAttributeMaxDynamicSharedMemorySize, SMEM_BYTES);
    blinear_fused<<<grid, 256, SMEM_BYTES>>>(x, W, b, out, nTiles);
}

// round 7
// speedup vs baseline: 1.3053x; 1.2003x over previous
#include <cuda_runtime.h>
#include <cuda_fp16.h>
#include <cstdint>

#define SM_STRIDE 136            // fp16 elems per smem row (conflict-free ldmatrix)

// smem byte offsets
#define WHI_OFF   0
#define XHI_OFF   (WHI_OFF + 128 * SM_STRIDE * 2)   // 34816
#define XLO_OFF   (XHI_OFF + 64 * SM_STRIDE * 2)    // +17408
#define XN2_OFF   (XLO_OFF + 64 * SM_STRIDE * 2)    // float[64]
#define HV_OFF    (XN2_OFF + 256)                   // float[128]
#define RED1_OFF  (HV_OFF  + 512)                   // float4[4][2][8] = 1024 B
#define RED2_OFF  (RED1_OFF + 1024)                 // float2[4][2][8] = 512 B
#define SC_OFF    (RED2_OFF + 512)                  // float[4]
#define SMEM_BYTES (SC_OFF + 16)                    // ~73 KB -> 2 CTAs/SM

#define MINN  1e-15f
#define MAXN  0.996f
#define ATLIM (1.0f - 1e-7f)

#define LDSM4(R, addr)                                                        \
    asm volatile("ldmatrix.sync.aligned.m8n8.x4.shared.b16 {%0,%1,%2,%3}, [%4];" \
                 : "=r"((R)[0]), "=r"((R)[1]), "=r"((R)[2]), "=r"((R)[3])     \
                 : "r"(addr) : "memory")

#define PAIR_BAR() asm volatile("bar.sync %0, 64;" :: "r"(barid) : "memory")

__device__ __forceinline__ void mma16816(float* d, const uint32_t* a, const uint32_t* b) {
    asm volatile(
        "mma.sync.aligned.m16n8k16.row.col.f32.f16.f16.f32 "
        "{%0,%1,%2,%3}, {%4,%5,%6,%7}, {%8,%9}, {%0,%1,%2,%3};"
        : "+f"(d[0]), "+f"(d[1]), "+f"(d[2]), "+f"(d[3])
        : "r"(a[0]), "r"(a[1]), "r"(a[2]), "r"(a[3]), "r"(b[0]), "r"(b[1]));
}

__device__ __forceinline__ float artanh_c(float x) {
    float xc = fminf(x, ATLIM);
    return 0.5f * (log1pf(xc) - log1pf(-xc));
}

__device__ __forceinline__ void row_chain(float S2, float D, float xn2v, float y2,
                                          float& pa, float& pb, float& Lr) {
    float xn  = fmaxf(sqrtf(xn2v), MINN);
    float mxn = fmaxf(sqrtf(S2), MINN);
    float atx = artanh_c(xn);
    float r1  = tanhf(mxn / xn * atx);
    float scale1 = r1 / mxn;
    float resn = r1;
    float pn = fmaxf(resn, MINN);
    if (pn > MAXN) { scale1 *= MAXN / pn; resn = MAXN; }
    float x2 = resn * resn;
    float xy = scale1 * D;
    float num1 = 1.f + 2.f*xy + y2;
    float den  = fmaxf(1.f + 2.f*xy + x2*y2, MINN);
    float aC = num1 / den;
    float bC = (1.f - x2) / den;
    float o2n2 = aC*aC*x2 + 2.f*aC*bC*xy + bC*bC*y2;
    float o2n  = sqrtf(fmaxf(o2n2, 0.f));
    float g = 1.f;
    float pn2 = fmaxf(o2n, MINN);
    if (pn2 > MAXN) { g = MAXN / pn2; pn2 = MAXN; }
    Lr = artanh_c(pn2) / pn2;
    pa = g * aC * scale1;
    pb = g * bC;
}

__device__ __forceinline__ float final_scale(float ps, float Lr) {
    float P  = sqrtf(fmaxf(ps, 0.f));
    float un = fmaxf(Lr * P, MINN);
    float th = tanhf(un);
    float f  = th / un * Lr;
    if (th > MAXN) f *= MAXN / th;
    return f;
}

// x: fp16 hi/lo split (residual ~2^-22) into padded-stride smem
__device__ __forceinline__ void split_store_x(__half* hi, __half* lo,
                                              int row, int col, float4 v) {
    __half2 h01 = __floats2half2_rn(v.x, v.y);
    __half2 h23 = __floats2half2_rn(v.z, v.w);
    float2 b01 = __half22float2(h01);
    float2 b23 = __half22float2(h23);
    __half2 l01 = __floats2half2_rn(v.x - b01.x, v.y - b01.y);
    __half2 l23 = __floats2half2_rn(v.z - b23.x, v.w - b23.y);
    uint2 ph, pl;
    ph.x = *reinterpret_cast<uint32_t*>(&h01);
    ph.y = *reinterpret_cast<uint32_t*>(&h23);
    pl.x = *reinterpret_cast<uint32_t*>(&l01);
    pl.y = *reinterpret_cast<uint32_t*>(&l23);
    *(uint2*)(hi + row * SM_STRIDE + col) = ph;
    *(uint2*)(lo + row * SM_STRIDE + col) = pl;
}

// W: single fp16 (rn)
__device__ __forceinline__ void store_w(__half* hi, int row, int col, float4 v) {
    __half2 h01 = __floats2half2_rn(v.x, v.y);
    __half2 h23 = __floats2half2_rn(v.z, v.w);
    uint2 ph;
    ph.x = *reinterpret_cast<uint32_t*>(&h01);
    ph.y = *reinterpret_cast<uint32_t*>(&h23);
    *(uint2*)(hi + row * SM_STRIDE + col) = ph;
}

__global__ void __launch_bounds__(256, 2)
blinear_fused(const float* __restrict__ X, const float* __restrict__ W,
              const float* __restrict__ B, float* __restrict__ OUT, int nTiles)
{
    extern __shared__ char smem[];
    __half* ws_hi = (__half*)(smem + WHI_OFF);
    __half* xs_hi = (__half*)(smem + XHI_OFF);
    __half* xs_lo = (__half*)(smem + XLO_OFF);
    float* xn2_s = (float*)(smem + XN2_OFF);
    float* hvec  = (float*)(smem + HV_OFF);
    float* red1  = (float*)(smem + RED1_OFF);
    float* red2  = (float*)(smem + RED2_OFF);
    float* SC    = (float*)(smem + SC_OFF);

    const int tid  = threadIdx.x;
    const int lane = tid & 31;
    const int w    = tid >> 5;   // 0..7
    const int pr   = w >> 1;     // pair 0..3 : rows 16*pr .. 16*pr+15
    const int wh   = w & 1;      // col half  : cols 64*wh .. 64*wh+63
    const int tq   = lane & 3;
    const int q    = lane >> 2;
    const int barid = 1 + pr;
    const int rbase = 16*pr + 8*wh;   // this warp's 8 x-rows within the tile

    // ---- once per CTA: W (128x128) -> fp16 in smem ----
    #pragma unroll
    for (int j = 0; j < 16; ++j) {
        int row = j * 8 + w;
        float4 wv = *(const float4*)(W + (size_t)row * 128 + lane * 4);
        store_w(ws_hi, row, lane * 4, wv);
    }

    // ---- once per CTA: hyp_bias h = proj(expmap0(b)) (warp 0) ----
    if (w == 0) {
        float4 bv = *(const float4*)(B + lane * 4);
        float sq = bv.x*bv.x + bv.y*bv.y + bv.z*bv.z + bv.w*bv.w;
        #pragma unroll
        for (int o = 16; o; o >>= 1) sq += __shfl_xor_sync(0xffffffffu, sq, o);
        float bn2 = sq;
        float bn  = fmaxf(sqrtf(bn2), MINN);
        float th  = tanhf(bn);
        float hs  = th / bn;
        float hn  = hs * sqrtf(bn2);
        float pn  = fmaxf(hn, MINN);
        if (pn > MAXN) hs *= MAXN / pn;
        if (lane == 0) SC[0] = hs * hs * bn2;
        *(float4*)(hvec + lane * 4) =
            make_float4(hs*bv.x, hs*bv.y, hs*bv.z, hs*bv.w);
    }
    __syncthreads();

    const float y2 = SC[0];

    // preload h slice for this warp's 64 columns (constant across tiles)
    float hv[8][2];
    #pragma unroll
    for (int nt = 0; nt < 8; ++nt) {
        int c = 64*wh + 8*nt + 2*tq;
        hv[nt][0] = hvec[c]; hv[nt][1] = hvec[c + 1];
    }

    uint32_t s_xhi = (uint32_t)__cvta_generic_to_shared(xs_hi);
    uint32_t s_xlo = (uint32_t)__cvta_generic_to_shared(xs_lo);
    uint32_t s_whi = (uint32_t)__cvta_generic_to_shared(ws_hi);

    // A fragment address: pair rows 16*pr..16*pr+15
    const uint32_t aoff = (uint32_t)(((16*pr + (lane & 15)) * SM_STRIDE + (lane >> 4) * 8) * 2);
    // B fragment addresses: 4 n16-groups covering this warp's 64 cols
    const int bg  = lane >> 3;
    const int b_n = ((bg >> 1) << 3) + (lane & 7);
    const int b_k = (bg & 1) * 8;
    uint32_t boff[4];
    #pragma unroll
    for (int g = 0; g < 4; ++g)
        boff[g] = (uint32_t)(((64*wh + 16*g + b_n) * SM_STRIDE + b_k) * 2);

    // exchange buffer slots
    float4* r1_me = (float4*)(red1 + ((pr*2 + wh    )*8 + q) * 4);
    float4* r1_ot = (float4*)(red1 + ((pr*2 + (wh^1))*8 + q) * 4);
    float2* r2_me = (float2*)(red2 + ((pr*2 + wh    )*8 + q) * 2);
    float2* r2_ot = (float2*)(red2 + ((pr*2 + (wh^1))*8 + q) * 2);

    const int rl0 = 16*pr + q;       // local tile row for acc elems 0,1
    const int rl1 = rl0 + 8;         // local tile row for acc elems 2,3

    // ================= persistent tile loop =================
    for (int tile = blockIdx.x; tile < nTiles; tile += gridDim.x) {
        const size_t tileRow = (size_t)tile * 64;

        // ---- load this warp's 8 rows (full 128 cols), norms, fp16 split ----
        #pragma unroll
        for (int j = 0; j < 8; ++j) {
            int rloc = rbase + j;
            float4 v = *(const float4*)(X + (tileRow + rloc) * 128 + lane * 4);
            float sq = v.x*v.x + v.y*v.y + v.z*v.z + v.w*v.w;
            #pragma unroll
            for (int o = 16; o; o >>= 1) sq += __shfl_xor_sync(0xffffffffu, sq, o);
            if (lane == 0) xn2_s[rloc] = sq;
            split_store_x(xs_hi, xs_lo, rloc, lane * 4, v);
        }

        // L2 prefetch next tile's rows for this warp
        {
            int nt2 = tile + gridDim.x;
            if (nt2 < nTiles) {
                const float* pf = X + ((size_t)nt2 * 64 + rbase) * 128
                                    + (size_t)lane * 32;
                asm volatile("prefetch.global.L2 [%0];" :: "l"(pf));
            }
        }

        PAIR_BAR();   // A: xs + xn2 visible within pair

        // ---- MMA: mx = (ah + al) @ Wh^T  (2 fp16 terms) ----
        float acc[8][4];
        #pragma unroll
        for (int nt = 0; nt < 8; ++nt)
            #pragma unroll
            for (int r = 0; r < 4; ++r) acc[nt][r] = 0.f;

        #pragma unroll
        for (int k = 0; k < 8; ++k) {
            const uint32_t kb = k * 32;
            uint32_t ah[4], al[4];
            LDSM4(ah, s_xhi + aoff + kb);
            LDSM4(al, s_xlo + aoff + kb);
            uint32_t bh[4][4];
            #pragma unroll
            for (int g = 0; g < 4; ++g)
                LDSM4(bh[g], s_whi + boff[g] + kb);
            #pragma unroll
            for (int nt = 0; nt < 8; ++nt) {
                const int g = nt >> 1, o = (nt & 1) * 2;
                mma16816(acc[nt], ah, &bh[g][o]);
                mma16816(acc[nt], al, &bh[g][o]);
            }
        }

        // ---- phase 1: per-row sum(mx^2), sum(mx*h) over this warp's 64 cols ----
        float sq0 = 0.f, dh0 = 0.f, sq1 = 0.f, dh1 = 0.f;
        #pragma unroll
        for (int nt = 0; nt < 8; ++nt) {
            float v0 = acc[nt][0], v1 = acc[nt][1];
            float v2 = acc[nt][2], v3 = acc[nt][3];
            sq0 = fmaf(v0, v0, fmaf(v1, v1, sq0));
            dh0 = fmaf(v0, hv[nt][0], fmaf(v1, hv[nt][1], dh0));
            sq1 = fmaf(v2, v2, fmaf(v3, v3, sq1));
            dh1 = fmaf(v2, hv[nt][0], fmaf(v3, hv[nt][1], dh1));
        }
        #pragma unroll
        for (int o = 1; o <= 2; o <<= 1) {
            sq0 += __shfl_xor_sync(0xffffffffu, sq0, o);
            dh0 += __shfl_xor_sync(0xffffffffu, dh0, o);
            sq1 += __shfl_xor_sync(0xffffffffu, sq1, o);
            dh1 += __shfl_xor_sync(0xffffffffu, dh1, o);
        }
        if (tq == 0) *r1_me = make_float4(sq0, dh0, sq1, dh1);
        PAIR_BAR();   // B
        float4 ot = *r1_ot;
        float S2_0 = sq0 + ot.x, D0 = dh0 + ot.y;
        float S2_1 = sq1 + ot.z, D1 = dh1 + ot.w;

        // ---- per-row scalar chain (in registers, per-quad redundant) ----
        float pa0, pb0, Lr0, pa1, pb1, Lr1;
        row_chain(S2_0, D0, xn2_s[rl0], y2, pa0, pb0, Lr0);
        row_chain(S2_1, D1, xn2_s[rl1], y2, pa1, pb1, Lr1);

        // ---- phase 2: val = pa*mx + pb*h ; sum(relu(val)^2) ----
        float ps0 = 0.f, ps1 = 0.f;
        #pragma unroll
        for (int nt = 0; nt < 8; ++nt) {
            float v0 = fmaf(pa0, acc[nt][0], pb0 * hv[nt][0]);
            float v1 = fmaf(pa0, acc[nt][1], pb0 * hv[nt][1]);
            float v2 = fmaf(pa1, acc[nt][2], pb1 * hv[nt][0]);
            float v3 = fmaf(pa1, acc[nt][3], pb1 * hv[nt][1]);
            acc[nt][0] = v0; acc[nt][1] = v1; acc[nt][2] = v2; acc[nt][3] = v3;
            float p0 = fmaxf(v0, 0.f), p1 = fmaxf(v1, 0.f);
            float p2 = fmaxf(v2, 0.f), p3 = fmaxf(v3, 0.f);
            ps0 = fmaf(p0, p0, fmaf(p1, p1, ps0));
            ps1 = fmaf(p2, p2, fmaf(p3, p3, ps1));
        }
        #pragma unroll
        for (int o = 1; o <= 2; o <<= 1) {
            ps0 += __shfl_xor_sync(0xffffffffu, ps0, o);
            ps1 += __shfl_xor_sync(0xffffffffu, ps1, o);
        }
        if (tq == 0) *r2_me = make_float2(ps0, ps1);
        PAIR_BAR();   // C
        float2 ot2 = *r2_ot;
        float fs0 = final_scale(ps0 + ot2.x, Lr0);
        float fs1 = final_scale(ps1 + ot2.y, Lr1);

        // ---- store: out = fs * relu(val) ----
        float* outp = OUT + (tileRow + rl0) * 128 + 64*wh + 2*tq;
        #pragma unroll
        for (int nt = 0; nt < 8; ++nt) {
            float2 o0, o1;
            o0.x = fs0 * fmaxf(acc[nt][0], 0.f);
            o0.y = fs0 * fmaxf(acc[nt][1], 0.f);
            o1.x = fs1 * fmaxf(acc[nt][2], 0.f);
            o1.y = fs1 * fmaxf(acc[nt][3], 0.f);
            *(float2*)(outp + 8*nt)        = o0;
            *(float2*)(outp + 1024 + 8*nt) = o1;   // row rl1 = rl0 + 8
        }
        // cross-iteration smem reuse is ordered by the three pair barriers
    }
}

extern "C" void kernel_launch(void* const* d_in, const int* in_sizes, int n_in,
                              void* d_out, int out_size) {
    const float* x = (const float*)d_in[0];
    const float* W = (const float*)d_in[1];
    const float* b = (const float*)d_in[2];
    float* out = (float*)d_out;

    int nRows  = in_sizes[0] / 128;      // 524288
    int nTiles = nRows / 64;             // 8192

    int sms = 148;
    cudaDeviceGetAttribute(&sms, cudaDevAttrMultiProcessorCount, 0);
    int grid = 2 * sms;                  // 2 persistent CTAs per SM
    if (grid > nTiles) grid = nTiles;

    cudaFuncSetAttribute(blinear_fused,
                         cudaFuncAttributeMaxDynamicSharedMemorySize, SMEM_BYTES);
    blinear_fused<<<grid, 256, SMEM_BYTES>>>(x, W, b, out, nTiles);
}

// round 8
// speedup vs baseline: 1.6350x; 1.2526x over previous
#include <cuda_runtime.h>
#include <cuda_fp16.h>
#include <cstdint>

#define SM_STRIDE 136            // fp16 elems per smem row (conflict-free ldmatrix)

// smem byte offsets
#define WS_OFF    0                                  // W fp16: 128*136*2 = 34816
#define XS_OFF    34816                              // x fp16: 128 rows
#define XN2_OFF   (XS_OFF + 128 * SM_STRIDE * 2)     // float[128]
#define HV_OFF    (XN2_OFF + 512)                    // float[128]
#define RED1_OFF  (HV_OFF  + 512)                    // float4[4][2][2][8] = 2048 B
#define RED2_OFF  (RED1_OFF + 2048)                  // float2[4][2][2][8] = 1024 B
#define SC_OFF    (RED2_OFF + 1024)                  // float[4]
#define SMEM_BYTES (SC_OFF + 16)                     // ~72 KB -> 2 CTAs/SM

#define MINN  1e-15f
#define MAXN  0.996f
#define ATLIM (1.0f - 1e-7f)

#define LDSM4(R, addr)                                                        \
    asm volatile("ldmatrix.sync.aligned.m8n8.x4.shared.b16 {%0,%1,%2,%3}, [%4];" \
                 : "=r"((R)[0]), "=r"((R)[1]), "=r"((R)[2]), "=r"((R)[3])     \
                 : "r"(addr) : "memory")

#define PAIR_BAR() asm volatile("bar.sync %0, 64;" :: "r"(barid) : "memory")

__device__ __forceinline__ void mma16816(float* d, const uint32_t* a, const uint32_t* b) {
    asm volatile(
        "mma.sync.aligned.m16n8k16.row.col.f32.f16.f16.f32 "
        "{%0,%1,%2,%3}, {%4,%5,%6,%7}, {%8,%9}, {%0,%1,%2,%3};"
        : "+f"(d[0]), "+f"(d[1]), "+f"(d[2]), "+f"(d[3])
        : "r"(a[0]), "r"(a[1]), "r"(a[2]), "r"(a[3]), "r"(b[0]), "r"(b[1]));
}

__device__ __forceinline__ float artanh_c(float x) {
    float xc = fminf(x, ATLIM);
    return 0.5f * (log1pf(xc) - log1pf(-xc));
}

__device__ __forceinline__ void row_chain(float S2, float D, float xn2v, float y2,
                                          float& pa, float& pb, float& Lr) {
    float xn  = fmaxf(sqrtf(xn2v), MINN);
    float mxn = fmaxf(sqrtf(S2), MINN);
    float atx = artanh_c(xn);
    float r1  = tanhf(mxn / xn * atx);
    float scale1 = r1 / mxn;
    float resn = r1;
    float pn = fmaxf(resn, MINN);
    if (pn > MAXN) { scale1 *= MAXN / pn; resn = MAXN; }
    float x2 = resn * resn;
    float xy = scale1 * D;
    float num1 = 1.f + 2.f*xy + y2;
    float den  = fmaxf(1.f + 2.f*xy + x2*y2, MINN);
    float aC = num1 / den;
    float bC = (1.f - x2) / den;
    float o2n2 = aC*aC*x2 + 2.f*aC*bC*xy + bC*bC*y2;
    float o2n  = sqrtf(fmaxf(o2n2, 0.f));
    float g = 1.f;
    float pn2 = fmaxf(o2n, MINN);
    if (pn2 > MAXN) { g = MAXN / pn2; pn2 = MAXN; }
    Lr = artanh_c(pn2) / pn2;
    pa = g * aC * scale1;
    pb = g * bC;
}

__device__ __forceinline__ float final_scale(float ps, float Lr) {
    float P  = sqrtf(fmaxf(ps, 0.f));
    float un = fmaxf(Lr * P, MINN);
    float th = tanhf(un);
    float f  = th / un * Lr;
    if (th > MAXN) f *= MAXN / th;
    return f;
}

// fp32x4 -> fp16x4 (rn) into padded-stride smem
__device__ __forceinline__ void store_h16(__half* dst, int row, int col, float4 v) {
    __half2 h01 = __floats2half2_rn(v.x, v.y);
    __half2 h23 = __floats2half2_rn(v.z, v.w);
    uint2 ph;
    ph.x = *reinterpret_cast<uint32_t*>(&h01);
    ph.y = *reinterpret_cast<uint32_t*>(&h23);
    *(uint2*)(dst + row * SM_STRIDE + col) = ph;
}

__global__ void __launch_bounds__(256, 2)
blinear_fused(const float* __restrict__ X, const float* __restrict__ W,
              const float* __restrict__ B, float* __restrict__ OUT, int nTiles)
{
    extern __shared__ char smem[];
    __half* ws    = (__half*)(smem + WS_OFF);
    __half* xs    = (__half*)(smem + XS_OFF);
    float* xn2_s  = (float*)(smem + XN2_OFF);
    float* hvec   = (float*)(smem + HV_OFF);
    float4* red1  = (float4*)(smem + RED1_OFF);
    float2* red2  = (float2*)(smem + RED2_OFF);
    float* SC     = (float*)(smem + SC_OFF);

    const int tid  = threadIdx.x;
    const int lane = tid & 31;
    const int w    = tid >> 5;   // 0..7
    const int pr   = w >> 1;     // pair 0..3 : rows 32*pr .. 32*pr+31
    const int wh   = w & 1;      // col half  : cols 64*wh .. 64*wh+63
    const int tq   = lane & 3;
    const int q    = lane >> 2;
    const int barid = 1 + pr;
    const int rbase = 32*pr + 16*wh;   // this warp's 16 x-rows within the tile

    // ---- once per CTA: W (128x128) -> fp16 in smem ----
    #pragma unroll
    for (int j = 0; j < 16; ++j) {
        int row = j * 8 + w;
        float4 wv = *(const float4*)(W + (size_t)row * 128 + lane * 4);
        store_h16(ws, row, lane * 4, wv);
    }

    // ---- once per CTA: hyp_bias h = proj(expmap0(b)) (warp 0) ----
    if (w == 0) {
        float4 bv = *(const float4*)(B + lane * 4);
        float sq = bv.x*bv.x + bv.y*bv.y + bv.z*bv.z + bv.w*bv.w;
        #pragma unroll
        for (int o = 16; o; o >>= 1) sq += __shfl_xor_sync(0xffffffffu, sq, o);
        float bn2 = sq;
        float bn  = fmaxf(sqrtf(bn2), MINN);
        float th  = tanhf(bn);
        float hs  = th / bn;
        float hn  = hs * sqrtf(bn2);
        float pn  = fmaxf(hn, MINN);
        if (pn > MAXN) hs *= MAXN / pn;
        if (lane == 0) SC[0] = hs * hs * bn2;
        *(float4*)(hvec + lane * 4) =
            make_float4(hs*bv.x, hs*bv.y, hs*bv.z, hs*bv.w);
    }
    __syncthreads();

    const float y2 = SC[0];

    // preload h slice for this warp's 64 columns (constant across tiles)
    float hv[8][2];
    #pragma unroll
    for (int nt = 0; nt < 8; ++nt) {
        int c = 64*wh + 8*nt + 2*tq;
        hv[nt][0] = hvec[c]; hv[nt][1] = hvec[c + 1];
    }

    uint32_t s_xs = (uint32_t)__cvta_generic_to_shared(xs);
    uint32_t s_ws = (uint32_t)__cvta_generic_to_shared(ws);

    // A fragment addresses: pair rows 32*pr..32*pr+31 (two m16 frags)
    const uint32_t aoff0 = (uint32_t)(((32*pr + (lane & 15)) * SM_STRIDE + (lane >> 4) * 8) * 2);
    const uint32_t aoff1 = aoff0 + 16 * SM_STRIDE * 2;
    // B fragment addresses: 4 n16-groups covering this warp's 64 cols
    const int bg  = lane >> 3;
    const int b_n = ((bg >> 1) << 3) + (lane & 7);
    const int b_k = (bg & 1) * 8;
    uint32_t boff[4];
    #pragma unroll
    for (int g = 0; g < 4; ++g)
        boff[g] = (uint32_t)(((64*wh + 16*g + b_n) * SM_STRIDE + b_k) * 2);

    // exchange buffer slots: index = ((pr*2 + wh)*2 + mt)*8 + q
    const int slot_me = (pr*2 + wh )*2*8;
    const int slot_ot = (pr*2 + (wh^1))*2*8;

    // ================= persistent tile loop (128-row CTA tiles) =============
    for (int tile = blockIdx.x; tile < nTiles; tile += gridDim.x) {
        const size_t tileRow = (size_t)tile * 128;

        // ---- load this warp's 16 rows (full 128 cols), norms, fp16 cvt ----
        #pragma unroll
        for (int j = 0; j < 16; ++j) {
            int rloc = rbase + j;
            float4 v = *(const float4*)(X + (tileRow + rloc) * 128 + lane * 4);
            float sq = v.x*v.x + v.y*v.y + v.z*v.z + v.w*v.w;
            #pragma unroll
            for (int o = 16; o; o >>= 1) sq += __shfl_xor_sync(0xffffffffu, sq, o);
            if (lane == 0) xn2_s[rloc] = sq;
            store_h16(xs, rloc, lane * 4, v);
        }

        // L2 prefetch next tile's 16 rows for this warp (8 KB)
        {
            int nt2 = tile + gridDim.x;
            if (nt2 < nTiles) {
                const float* pf = X + ((size_t)nt2 * 128 + rbase) * 128
                                    + (size_t)lane * 64;
                asm volatile("prefetch.global.L2 [%0];" :: "l"(pf));
                asm volatile("prefetch.global.L2 [%0];" :: "l"(pf + 32));
            }
        }

        PAIR_BAR();   // A: xs + xn2 visible within pair

        // ---- MMA: 32 rows x 64 cols, single fp16 term ----
        float acc[2][8][4];
        #pragma unroll
        for (int mt = 0; mt < 2; ++mt)
            #pragma unroll
            for (int nt = 0; nt < 8; ++nt)
                #pragma unroll
                for (int r = 0; r < 4; ++r) acc[mt][nt][r] = 0.f;

        #pragma unroll
        for (int k = 0; k < 8; ++k) {
            const uint32_t kb = k * 32;
            uint32_t ah0[4], ah1[4];
            LDSM4(ah0, s_xs + aoff0 + kb);
            LDSM4(ah1, s_xs + aoff1 + kb);
            uint32_t bh[4][4];
            #pragma unroll
            for (int g = 0; g < 4; ++g)
                LDSM4(bh[g], s_ws + boff[g] + kb);
            #pragma unroll
            for (int nt = 0; nt < 8; ++nt) {
                const int g = nt >> 1, o = (nt & 1) * 2;
                mma16816(acc[0][nt], ah0, &bh[g][o]);
                mma16816(acc[1][nt], ah1, &bh[g][o]);
            }
        }

        // ---- phase 1: per-row sum(mx^2), sum(mx*h) over this warp's 64 cols ----
        float S2[2][2], Dd[2][2];
        #pragma unroll
        for (int mt = 0; mt < 2; ++mt) {
            float sq0 = 0.f, dh0 = 0.f, sq1 = 0.f, dh1 = 0.f;
            #pragma unroll
            for (int nt = 0; nt < 8; ++nt) {
                float v0 = acc[mt][nt][0], v1 = acc[mt][nt][1];
                float v2 = acc[mt][nt][2], v3 = acc[mt][nt][3];
                sq0 = fmaf(v0, v0, fmaf(v1, v1, sq0));
                dh0 = fmaf(v0, hv[nt][0], fmaf(v1, hv[nt][1], dh0));
                sq1 = fmaf(v2, v2, fmaf(v3, v3, sq1));
                dh1 = fmaf(v2, hv[nt][0], fmaf(v3, hv[nt][1], dh1));
            }
            #pragma unroll
            for (int o = 1; o <= 2; o <<= 1) {
                sq0 += __shfl_xor_sync(0xffffffffu, sq0, o);
                dh0 += __shfl_xor_sync(0xffffffffu, dh0, o);
                sq1 += __shfl_xor_sync(0xffffffffu, sq1, o);
                dh1 += __shfl_xor_sync(0xffffffffu, dh1, o);
            }
            S2[mt][0] = sq0; Dd[mt][0] = dh0;
            S2[mt][1] = sq1; Dd[mt][1] = dh1;
            if (tq == 0) red1[slot_me + mt*8 + q] = make_float4(sq0, dh0, sq1, dh1);
        }
        PAIR_BAR();   // B

        // ---- per-row scalar chain: 4 rows/thread (per-quad redundant) ----
        float pa[2][2], pb[2][2], Lr[2][2];
        #pragma unroll
        for (int mt = 0; mt < 2; ++mt) {
            float4 ot = red1[slot_ot + mt*8 + q];
            #pragma unroll
            for (int rh = 0; rh < 2; ++rh) {
                int rloc = 32*pr + 16*mt + 8*rh + q;
                float s2 = S2[mt][rh] + (rh ? ot.z : ot.x);
                float dd = Dd[mt][rh] + (rh ? ot.w : ot.y);
                row_chain(s2, dd, xn2_s[rloc], y2, pa[mt][rh], pb[mt][rh], Lr[mt][rh]);
            }
        }

        // ---- phase 2: val = pa*mx + pb*h ; sum(relu(val)^2) ----
        float psr[2][2];
        #pragma unroll
        for (int mt = 0; mt < 2; ++mt) {
            #pragma unroll
            for (int rh = 0; rh < 2; ++rh) {
                float ps = 0.f;
                float pav = pa[mt][rh], pbv = pb[mt][rh];
                #pragma unroll
                for (int nt = 0; nt < 8; ++nt) {
                    float v0 = fmaf(pav, acc[mt][nt][2*rh],     pbv * hv[nt][0]);
                    float v1 = fmaf(pav, acc[mt][nt][2*rh + 1], pbv * hv[nt][1]);
                    acc[mt][nt][2*rh]     = v0;
                    acc[mt][nt][2*rh + 1] = v1;
                    float p0 = fmaxf(v0, 0.f), p1 = fmaxf(v1, 0.f);
                    ps = fmaf(p0, p0, fmaf(p1, p1, ps));
                }
                ps += __shfl_xor_sync(0xffffffffu, ps, 1);
                ps += __shfl_xor_sync(0xffffffffu, ps, 2);
                psr[mt][rh] = ps;
            }
            if (tq == 0) red2[slot_me + mt*8 + q] = make_float2(psr[mt][0], psr[mt][1]);
        }
        PAIR_BAR();   // C

        // ---- final scale + store ----
        #pragma unroll
        for (int mt = 0; mt < 2; ++mt) {
            float2 ot2 = red2[slot_ot + mt*8 + q];
            #pragma unroll
            for (int rh = 0; rh < 2; ++rh) {
                int rloc = 32*pr + 16*mt + 8*rh + q;
                float fs = final_scale(psr[mt][rh] + (rh ? ot2.y : ot2.x), Lr[mt][rh]);
                float* outp = OUT + (tileRow + rloc) * 128 + 64*wh + 2*tq;
                #pragma unroll
                for (int nt = 0; nt < 8; ++nt) {
                    float2 o;
                    o.x = fs * fmaxf(acc[mt][nt][2*rh],     0.f);
                    o.y = fs * fmaxf(acc[mt][nt][2*rh + 1], 0.f);
                    *(float2*)(outp + 8*nt) = o;
                }
            }
        }
        // cross-iteration smem reuse is ordered by the three pair barriers
    }
}

extern "C" void kernel_launch(void* const* d_in, const int* in_sizes, int n_in,
                              void* d_out, int out_size) {
    const float* x = (const float*)d_in[0];
    const float* W = (const float*)d_in[1];
    const float* b = (const float*)d_in[2];
    float* out = (float*)d_out;

    int nRows  = in_sizes[0] / 128;      // 524288
    int nTiles = nRows / 128;            // 4096

    int sms = 148;
    cudaDeviceGetAttribute(&sms, cudaDevAttrMultiProcessorCount, 0);
    int grid = 2 * sms;                  // 2 persistent CTAs per SM
    if (grid > nTiles) grid = nTiles;

    cudaFuncSetAttribute(blinear_fused,
                         cudaFuncAttributeMaxDynamicSharedMemorySize, SMEM_BYTES);
    blinear_fused<<<grid, 256, SMEM_BYTES>>>(x, W, b, out, nTiles);
}

// round 9
// speedup vs baseline: 1.6554x; 1.0125x over previous
#include <cuda_runtime.h>
#include <cuda_fp16.h>
#include <cstdint>

#define SM_STRIDE 136            // fp16 elems per smem row (conflict-free ldmatrix)

// smem byte offsets
#define WS_OFF    0                                  // W fp16: 128*136*2 = 34816
#define XS_OFF    34816                              // x fp16: 128 rows
#define XN2_OFF   (XS_OFF + 128 * SM_STRIDE * 2)     // float[128]
#define DS_OFF    (XN2_OFF + 512)                    // float[128]  per-row D = <x,u>
#define US_OFF    (DS_OFF + 512)                     // float[128]  u = W^T h
#define HV_OFF    (US_OFF + 512)                     // float[128]
#define RED1_OFF  (HV_OFF + 512)                     // float2[128] = 1024
#define RED2_OFF  (RED1_OFF + 1024)                  // float2[128] = 1024
#define SC_OFF    (RED2_OFF + 1024)                  // float[4]
#define SMEM_BYTES (SC_OFF + 16)                     // ~74 KB -> 2 CTAs/SM

#define MINN  1e-15f
#define MAXN  0.996f
#define ATLIM (1.0f - 1e-7f)

#define LDSM4(R, addr)                                                        \
    asm volatile("ldmatrix.sync.aligned.m8n8.x4.shared.b16 {%0,%1,%2,%3}, [%4];" \
                 : "=r"((R)[0]), "=r"((R)[1]), "=r"((R)[2]), "=r"((R)[3])     \
                 : "r"(addr) : "memory")

#define PAIR_BAR() asm volatile("bar.sync %0, 64;" :: "r"(barid) : "memory")

__device__ __forceinline__ void mma16816(float* d, const uint32_t* a, const uint32_t* b) {
    asm volatile(
        "mma.sync.aligned.m16n8k16.row.col.f32.f16.f16.f32 "
        "{%0,%1,%2,%3}, {%4,%5,%6,%7}, {%8,%9}, {%0,%1,%2,%3};"
        : "+f"(d[0]), "+f"(d[1]), "+f"(d[2]), "+f"(d[3])
        : "r"(a[0]), "r"(a[1]), "r"(a[2]), "r"(a[3]), "r"(b[0]), "r"(b[1]));
}

__device__ __forceinline__ float artanh_c(float x) {
    float xc = fminf(x, ATLIM);
    return 0.5f * (log1pf(xc) - log1pf(-xc));
}

__device__ __forceinline__ void row_chain(float S2, float D, float xn2v, float y2,
                                          float& pa, float& pb, float& Lr) {
    float xn  = fmaxf(sqrtf(xn2v), MINN);
    float mxn = fmaxf(sqrtf(S2), MINN);
    float atx = artanh_c(xn);
    float r1  = tanhf(mxn / xn * atx);
    float scale1 = r1 / mxn;
    float resn = r1;
    float pn = fmaxf(resn, MINN);
    if (pn > MAXN) { scale1 *= MAXN / pn; resn = MAXN; }
    float x2 = resn * resn;
    float xy = scale1 * D;
    float num1 = 1.f + 2.f*xy + y2;
    float den  = fmaxf(1.f + 2.f*xy + x2*y2, MINN);
    float aC = num1 / den;
    float bC = (1.f - x2) / den;
    float o2n2 = aC*aC*x2 + 2.f*aC*bC*xy + bC*bC*y2;
    float o2n  = sqrtf(fmaxf(o2n2, 0.f));
    float g = 1.f;
    float pn2 = fmaxf(o2n, MINN);
    if (pn2 > MAXN) { g = MAXN / pn2; pn2 = MAXN; }
    Lr = artanh_c(pn2) / pn2;
    pa = g * aC * scale1;
    pb = g * bC;
}

__device__ __forceinline__ float final_scale(float ps, float Lr) {
    float P  = sqrtf(fmaxf(ps, 0.f));
    float un = fmaxf(Lr * P, MINN);
    float th = tanhf(un);
    float f  = th / un * Lr;
    if (th > MAXN) f *= MAXN / th;
    return f;
}

// fp32x4 -> fp16x4 (rn) into padded-stride smem
__device__ __forceinline__ void store_h16(__half* dst, int row, int col, float4 v) {
    __half2 h01 = __floats2half2_rn(v.x, v.y);
    __half2 h23 = __floats2half2_rn(v.z, v.w);
    uint2 ph;
    ph.x = *reinterpret_cast<uint32_t*>(&h01);
    ph.y = *reinterpret_cast<uint32_t*>(&h23);
    *(uint2*)(dst + row * SM_STRIDE + col) = ph;
}

__global__ void __launch_bounds__(256, 2)
blinear_fused(const float* __restrict__ X, const float* __restrict__ W,
              const float* __restrict__ B, float* __restrict__ OUT, int nTiles)
{
    extern __shared__ char smem[];
    __half* ws    = (__half*)(smem + WS_OFF);
    __half* xs    = (__half*)(smem + XS_OFF);
    float* xn2_s  = (float*)(smem + XN2_OFF);
    float* D_s    = (float*)(smem + DS_OFF);
    float* us     = (float*)(smem + US_OFF);
    float* hvec   = (float*)(smem + HV_OFF);
    float2* red1  = (float2*)(smem + RED1_OFF);
    float2* red2  = (float2*)(smem + RED2_OFF);
    float* SC     = (float*)(smem + SC_OFF);

    const int tid  = threadIdx.x;
    const int lane = tid & 31;
    const int w    = tid >> 5;   // 0..7
    const int pr   = w >> 1;     // pair 0..3 : rows 32*pr .. 32*pr+31
    const int wh   = w & 1;      // col half  : cols 64*wh .. 64*wh+63
    const int tq   = lane & 3;
    const int q    = lane >> 2;
    const int barid = 1 + pr;
    const int rbase = 32*pr + 16*wh;   // this warp's 16 x-rows within the tile
    const int lr   = lane >> 3;        // row-in-group 0..3 for restructured load
    const int lc   = lane & 7;         // col-lane 0..7

    // ---- once per CTA: W (128x128) -> fp16 in smem ----
    #pragma unroll
    for (int j = 0; j < 16; ++j) {
        int row = j * 8 + w;
        float4 wv = *(const float4*)(W + (size_t)row * 128 + lane * 4);
        store_h16(ws, row, lane * 4, wv);
    }

    // ---- once per CTA: hyp_bias h = proj(expmap0(b)) (warp 0) ----
    if (w == 0) {
        float4 bv = *(const float4*)(B + lane * 4);
        float sq = bv.x*bv.x + bv.y*bv.y + bv.z*bv.z + bv.w*bv.w;
        #pragma unroll
        for (int o = 16; o; o >>= 1) sq += __shfl_xor_sync(0xffffffffu, sq, o);
        float bn2 = sq;
        float bn  = fmaxf(sqrtf(bn2), MINN);
        float th  = tanhf(bn);
        float hs  = th / bn;
        float hn  = hs * sqrtf(bn2);
        float pn  = fmaxf(hn, MINN);
        if (pn > MAXN) hs *= MAXN / pn;
        if (lane == 0) SC[0] = hs * hs * bn2;
        *(float4*)(hvec + lane * 4) =
            make_float4(hs*bv.x, hs*bv.y, hs*bv.z, hs*bv.w);
    }
    __syncthreads();

    const float y2 = SC[0];
    const bool hasB = (y2 != 0.0f);   // uniform across grid

    // ---- once per CTA (only if bias nonzero): u = W^T h  (fp32, exact-form D) ----
    if (hasB && tid < 128) {
        float a = 0.f;
        for (int j = 0; j < 128; ++j)
            a = fmaf(hvec[j], W[(size_t)j * 128 + tid], a);
        us[tid] = a;
    }
    __syncthreads();

    uint32_t s_xs = (uint32_t)__cvta_generic_to_shared(xs);
    uint32_t s_ws = (uint32_t)__cvta_generic_to_shared(ws);

    // A fragment addresses: pair rows 32*pr..32*pr+31 (two m16 frags)
    const uint32_t aoff0 = (uint32_t)(((32*pr + (lane & 15)) * SM_STRIDE + (lane >> 4) * 8) * 2);
    const uint32_t aoff1 = aoff0 + 16 * SM_STRIDE * 2;
    // B fragment addresses: 4 n16-groups covering this warp's 64 cols
    const int bg  = lane >> 3;
    const int b_n = ((bg >> 1) << 3) + (lane & 7);
    const int b_k = (bg & 1) * 8;
    uint32_t boff[4];
    #pragma unroll
    for (int g = 0; g < 4; ++g)
        boff[g] = (uint32_t)(((64*wh + 16*g + b_n) * SM_STRIDE + b_k) * 2);

    // exchange buffer slots: index = slot*16 + mt*8 + q
    const int slot_me = (pr*2 + wh )*16;
    const int slot_ot = (pr*2 + (wh^1))*16;

    // ================= persistent tile loop (128-row CTA tiles) =============
    for (int tile = blockIdx.x; tile < nTiles; tile += gridDim.x) {
        const size_t tileRow = (size_t)tile * 128;

        // ---- load 16 rows: 4 row-groups x 8 lanes x 4 chunks (coalesced) ----
        // row = rbase + 4j + lr ; col = ((lc*4 + lr*8) & 31) + 32i (staggered)
        const int colbase = ((lc * 4) + (lr * 8)) & 31;
        #pragma unroll
        for (int j = 0; j < 4; ++j) {
            const int row = rbase + 4*j + lr;
            float sq = 0.f, dh = 0.f;
            #pragma unroll
            for (int i = 0; i < 4; ++i) {
                const int col = colbase + 32*i;
                float4 v = *(const float4*)(X + (tileRow + row) * 128 + col);
                sq = fmaf(v.x, v.x, fmaf(v.y, v.y, fmaf(v.z, v.z, fmaf(v.w, v.w, sq))));
                if (hasB) {
                    float4 u4 = *(const float4*)(us + col);
                    dh = fmaf(v.x, u4.x, fmaf(v.y, u4.y, fmaf(v.z, u4.z, fmaf(v.w, u4.w, dh))));
                }
                store_h16(xs, row, col, v);
            }
            // reduce over the 8 lanes of this row (bits 0..2)
            #pragma unroll
            for (int o = 1; o <= 4; o <<= 1) {
                sq += __shfl_xor_sync(0xffffffffu, sq, o);
                if (hasB) dh += __shfl_xor_sync(0xffffffffu, dh, o);
            }
            if (lc == 0) { xn2_s[row] = sq; D_s[row] = dh; }
        }

        // L2 prefetch next tile's 16 rows for this warp (8 KB)
        {
            int nt2 = tile + gridDim.x;
            if (nt2 < nTiles) {
                const float* pf = X + ((size_t)nt2 * 128 + rbase) * 128
                                    + (size_t)lane * 64;
                asm volatile("prefetch.global.L2 [%0];" :: "l"(pf));
                asm volatile("prefetch.global.L2 [%0];" :: "l"(pf + 32));
            }
        }

        PAIR_BAR();   // A: xs + xn2 + D visible within pair

        // ---- MMA: 32 rows x 64 cols, single fp16 term ----
        float acc[2][8][4];
        #pragma unroll
        for (int mt = 0; mt < 2; ++mt)
            #pragma unroll
            for (int nt = 0; nt < 8; ++nt)
                #pragma unroll
                for (int r = 0; r < 4; ++r) acc[mt][nt][r] = 0.f;

        #pragma unroll
        for (int k = 0; k < 8; ++k) {
            const uint32_t kb = k * 32;
            uint32_t ah0[4], ah1[4];
            LDSM4(ah0, s_xs + aoff0 + kb);
            LDSM4(ah1, s_xs + aoff1 + kb);
            uint32_t bh[4][4];
            #pragma unroll
            for (int g = 0; g < 4; ++g)
                LDSM4(bh[g], s_ws + boff[g] + kb);
            #pragma unroll
            for (int nt = 0; nt < 8; ++nt) {
                const int g = nt >> 1, o = (nt & 1) * 2;
                mma16816(acc[0][nt], ah0, &bh[g][o]);
                mma16816(acc[1][nt], ah1, &bh[g][o]);
            }
        }

        // ---- phase 1: per-row sum(mx^2) over this warp's 64 cols ----
        float S2[2][2];
        #pragma unroll
        for (int mt = 0; mt < 2; ++mt) {
            float sq0 = 0.f, sq1 = 0.f;
            #pragma unroll
            for (int nt = 0; nt < 8; ++nt) {
                sq0 = fmaf(acc[mt][nt][0], acc[mt][nt][0],
                      fmaf(acc[mt][nt][1], acc[mt][nt][1], sq0));
                sq1 = fmaf(acc[mt][nt][2], acc[mt][nt][2],
                      fmaf(acc[mt][nt][3], acc[mt][nt][3], sq1));
            }
            #pragma unroll
            for (int o = 1; o <= 2; o <<= 1) {
                sq0 += __shfl_xor_sync(0xffffffffu, sq0, o);
                sq1 += __shfl_xor_sync(0xffffffffu, sq1, o);
            }
            S2[mt][0] = sq0; S2[mt][1] = sq1;
            if (tq == 0) red1[slot_me + mt*8 + q] = make_float2(sq0, sq1);
        }
        PAIR_BAR();   // B

        // ---- per-row scalar chain: 4 rows/thread (per-quad redundant) ----
        float pa[2][2], pb[2][2], Lr[2][2];
        #pragma unroll
        for (int mt = 0; mt < 2; ++mt) {
            float2 ot = red1[slot_ot + mt*8 + q];
            #pragma unroll
            for (int rh = 0; rh < 2; ++rh) {
                int rloc = 32*pr + 16*mt + 8*rh + q;
                float s2 = S2[mt][rh] + (rh ? ot.y : ot.x);
                row_chain(s2, D_s[rloc], xn2_s[rloc], y2,
                          pa[mt][rh], pb[mt][rh], Lr[mt][rh]);
            }
        }

        // ---- phase 2: p = relu(pa*mx [+ pb*h]) ; sum(p^2) ; acc <- p ----
        float psr[2][2];
        if (!hasB) {
            #pragma unroll
            for (int mt = 0; mt < 2; ++mt) {
                #pragma unroll
                for (int rh = 0; rh < 2; ++rh) {
                    float ps = 0.f;
                    const float pav = pa[mt][rh];
                    #pragma unroll
                    for (int nt = 0; nt < 8; ++nt) {
                        float p0 = fmaxf(pav * acc[mt][nt][2*rh],     0.f);
                        float p1 = fmaxf(pav * acc[mt][nt][2*rh + 1], 0.f);
                        acc[mt][nt][2*rh]     = p0;
                        acc[mt][nt][2*rh + 1] = p1;
                        ps = fmaf(p0, p0, fmaf(p1, p1, ps));
                    }
                    ps += __shfl_xor_sync(0xffffffffu, ps, 1);
                    ps += __shfl_xor_sync(0xffffffffu, ps, 2);
                    psr[mt][rh] = ps;
                }
                if (tq == 0) red2[slot_me + mt*8 + q] = make_float2(psr[mt][0], psr[mt][1]);
            }
        } else {
            float hv[8][2];
            #pragma unroll
            for (int nt = 0; nt < 8; ++nt) {
                float2 hc = *(const float2*)(hvec + 64*wh + 8*nt + 2*tq);
                hv[nt][0] = hc.x; hv[nt][1] = hc.y;
            }
            #pragma unroll
            for (int mt = 0; mt < 2; ++mt) {
                #pragma unroll
                for (int rh = 0; rh < 2; ++rh) {
                    float ps = 0.f;
                    const float pav = pa[mt][rh], pbv = pb[mt][rh];
                    #pragma unroll
                    for (int nt = 0; nt < 8; ++nt) {
                        float p0 = fmaxf(fmaf(pav, acc[mt][nt][2*rh],     pbv * hv[nt][0]), 0.f);
                        float p1 = fmaxf(fmaf(pav, acc[mt][nt][2*rh + 1], pbv * hv[nt][1]), 0.f);
                        acc[mt][nt][2*rh]     = p0;
                        acc[mt][nt][2*rh + 1] = p1;
                        ps = fmaf(p0, p0, fmaf(p1, p1, ps));
                    }
                    ps += __shfl_xor_sync(0xffffffffu, ps, 1);
                    ps += __shfl_xor_sync(0xffffffffu, ps, 2);
                    psr[mt][rh] = ps;
                }
                if (tq == 0) red2[slot_me + mt*8 + q] = make_float2(psr[mt][0], psr[mt][1]);
            }
        }
        PAIR_BAR();   // C

        // ---- final scale + store (acc already relu'd) ----
        #pragma unroll
        for (int mt = 0; mt < 2; ++mt) {
            float2 ot2 = red2[slot_ot + mt*8 + q];
            #pragma unroll
            for (int rh = 0; rh < 2; ++rh) {
                int rloc = 32*pr + 16*mt + 8*rh + q;
                float fs = final_scale(psr[mt][rh] + (rh ? ot2.y : ot2.x), Lr[mt][rh]);
                float* outp = OUT + (tileRow + rloc) * 128 + 64*wh + 2*tq;
                #pragma unroll
                for (int nt = 0; nt < 8; ++nt) {
                    float2 o;
                    o.x = fs * acc[mt][nt][2*rh];
                    o.y = fs * acc[mt][nt][2*rh + 1];
                    *(float2*)(outp + 8*nt) = o;
                }
            }
        }
        // cross-iteration smem reuse is ordered by the three pair barriers
    }
}

extern "C" void kernel_launch(void* const* d_in, const int* in_sizes, int n_in,
                              void* d_out, int out_size) {
    const float* x = (const float*)d_in[0];
    const float* W = (const float*)d_in[1];
    const float* b = (const float*)d_in[2];
    float* out = (float*)d_out;

    int nRows  = in_sizes[0] / 128;      // 524288
    int nTiles = nRows / 128;            // 4096

    int sms = 148;
    cudaDeviceGetAttribute(&sms, cudaDevAttrMultiProcessorCount, 0);
    int grid = 2 * sms;                  // 2 persistent CTAs per SM
    if (grid > nTiles) grid = nTiles;

    cudaFuncSetAttribute(blinear_fused,
                         cudaFuncAttributeMaxDynamicSharedMemorySize, SMEM_BYTES);
    blinear_fused<<<grid, 256, SMEM_BYTES>>>(x, W, b, out, nTiles);
}